// round 2
// baseline (speedup 1.0000x reference)
#include <cuda_runtime.h>

#define NNODES 200000
#define AF 82
#define H 10
#define ED 6
#define STRIDE 12   // padded row: 48B, 16B-aligned -> 3x float4

__device__ float g_h[(size_t)NNODES * STRIDE];
__device__ float g_p[(size_t)NNODES * STRIDE];    // p = h @ Wg_top
__device__ float g_agg[(size_t)NNODES * STRIDE];

__device__ __forceinline__ float lrelu(float x) { return fmaxf(x, 0.1f * x); }

// ---------------------------------------------------------------------------
// init: h = lrelu(vertex @ Wi); p = h @ Wg_top.  Shared-staged coalesced reads.
// ---------------------------------------------------------------------------
#define IB 128
__global__ void init_kernel(const float* __restrict__ vertex,
                            const float* __restrict__ Wi,
                            const float* __restrict__ Wg, int n) {
    __shared__ float wi[AF * H];          // 820
    __shared__ float wg[H * H];           // 100 (top block of gather_weight)
    __shared__ float tile[IB * 83];       // pad 82->83: stride 83 mod 32 = 19, conflict-free
    for (int i = threadIdx.x; i < AF * H; i += blockDim.x) wi[i] = Wi[i];
    for (int i = threadIdx.x; i < H * H; i += blockDim.x) wg[i] = Wg[i];

    int base = blockIdx.x * IB;
    int cnt = min(IB, n - base);
    if (cnt <= 0) return;
    int total = cnt * AF;
    const float* vs = vertex + (size_t)base * AF;
    for (int i = threadIdx.x; i < total; i += blockDim.x)
        tile[(i / AF) * 83 + (i % AF)] = vs[i];
    __syncthreads();

    int t = threadIdx.x;
    if (t >= cnt) return;
    const float* row = tile + t * 83;
    float acc[H];
#pragma unroll
    for (int j = 0; j < H; j++) acc[j] = 0.f;
#pragma unroll 2
    for (int i = 0; i < AF; i++) {
        float v = row[i];
#pragma unroll
        for (int j = 0; j < H; j++) acc[j] += v * wi[i * H + j];
    }
    float h[H];
#pragma unroll
    for (int j = 0; j < H; j++) h[j] = lrelu(acc[j]);

    float pv[H];
#pragma unroll
    for (int j = 0; j < H; j++) {
        float a = 0.f;
#pragma unroll
        for (int i = 0; i < H; i++) a += h[i] * wg[i * H + j];
        pv[j] = a;
    }

    size_t off = (size_t)(base + t) * STRIDE;
    float4* hw = (float4*)(g_h + off);
    float4* pw = (float4*)(g_p + off);
    hw[0] = make_float4(h[0], h[1], h[2], h[3]);
    hw[1] = make_float4(h[4], h[5], h[6], h[7]);
    hw[2] = make_float4(h[8], h[9], 0.f, 0.f);
    pw[0] = make_float4(pv[0], pv[1], pv[2], pv[3]);
    pw[1] = make_float4(pv[4], pv[5], pv[6], pv[7]);
    pw[2] = make_float4(pv[8], pv[9], 0.f, 0.f);
}

// ---------------------------------------------------------------------------
// edge: msg = lrelu(p[src] + ef @ Wg_bot); agg[dst] += msg.  2 edges/thread.
// ---------------------------------------------------------------------------
__global__ void edge_kernel(const float4* __restrict__ ef4,
                            const int2* __restrict__ src2,
                            const int2* __restrict__ dst2,
                            const float* __restrict__ Wg, int ecnt) {
    __shared__ float w[ED * H];  // bottom block: Wg[(H+k)*H + j]
    for (int i = threadIdx.x; i < ED * H; i += blockDim.x) w[i] = Wg[H * H + i];
    __syncthreads();

    int pr = blockIdx.x * blockDim.x + threadIdx.x;
    int e0 = 2 * pr;
    if (e0 >= ecnt) return;
    bool full = (e0 + 1) < ecnt;

    int2 s, d;
    float evA[ED], evB[ED];
    if (full) {
        s = src2[pr];
        d = dst2[pr];
        float4 f0 = ef4[3 * pr], f1 = ef4[3 * pr + 1], f2 = ef4[3 * pr + 2];
        evA[0] = f0.x; evA[1] = f0.y; evA[2] = f0.z; evA[3] = f0.w; evA[4] = f1.x; evA[5] = f1.y;
        evB[0] = f1.z; evB[1] = f1.w; evB[2] = f2.x; evB[3] = f2.y; evB[4] = f2.z; evB[5] = f2.w;
    } else {
        const int* si = (const int*)src2;
        const int* di = (const int*)dst2;
        s.x = si[e0]; s.y = s.x;
        d.x = di[e0]; d.y = d.x;
        const float* eff = (const float*)ef4;
#pragma unroll
        for (int k = 0; k < ED; k++) { evA[k] = eff[(size_t)e0 * ED + k]; evB[k] = 0.f; }
    }

    const float4* pA = (const float4*)(g_p + (size_t)s.x * STRIDE);
    const float4* pB = (const float4*)(g_p + (size_t)s.y * STRIDE);
    float4 a0 = pA[0], a1 = pA[1], a2 = pA[2];
    float4 b0 = pB[0], b1 = pB[1], b2 = pB[2];
    float pa[H] = {a0.x, a0.y, a0.z, a0.w, a1.x, a1.y, a1.z, a1.w, a2.x, a2.y};
    float pb[H] = {b0.x, b0.y, b0.z, b0.w, b1.x, b1.y, b1.z, b1.w, b2.x, b2.y};

    float mA[H], mB[H];
#pragma unroll
    for (int j = 0; j < H; j++) {
        float accA = pa[j], accB = pb[j];
#pragma unroll
        for (int k = 0; k < ED; k++) {
            float wk = w[k * H + j];
            accA += evA[k] * wk;
            accB += evB[k] * wk;
        }
        mA[j] = lrelu(accA);
        mB[j] = lrelu(accB);
    }

    float* apA = g_agg + (size_t)d.x * STRIDE;
    asm volatile("red.global.add.v4.f32 [%0], {%1,%2,%3,%4};" ::"l"(apA),
                 "f"(mA[0]), "f"(mA[1]), "f"(mA[2]), "f"(mA[3]) : "memory");
    asm volatile("red.global.add.v4.f32 [%0], {%1,%2,%3,%4};" ::"l"(apA + 4),
                 "f"(mA[4]), "f"(mA[5]), "f"(mA[6]), "f"(mA[7]) : "memory");
    asm volatile("red.global.add.v2.f32 [%0], {%1,%2};" ::"l"(apA + 8),
                 "f"(mA[8]), "f"(mA[9]) : "memory");
    if (full) {
        float* apB = g_agg + (size_t)d.y * STRIDE;
        asm volatile("red.global.add.v4.f32 [%0], {%1,%2,%3,%4};" ::"l"(apB),
                     "f"(mB[0]), "f"(mB[1]), "f"(mB[2]), "f"(mB[3]) : "memory");
        asm volatile("red.global.add.v4.f32 [%0], {%1,%2,%3,%4};" ::"l"(apB + 4),
                     "f"(mB[4]), "f"(mB[5]), "f"(mB[6]), "f"(mB[7]) : "memory");
        asm volatile("red.global.add.v2.f32 [%0], {%1,%2};" ::"l"(apB + 8),
                     "f"(mB[8]), "f"(mB[9]) : "memory");
    }
}

// ---------------------------------------------------------------------------
// update: h' = lrelu(h @ Wu_top + agg @ Wu_bot); optionally p' = h' @ Wg_top
// ---------------------------------------------------------------------------
__global__ void update_kernel(const float* __restrict__ Wu,
                              const float* __restrict__ Wg,
                              float* __restrict__ out, int n,
                              int out_stride, int write_p) {
    __shared__ float wu[2 * H * H];  // 200
    __shared__ float wg[H * H];      // 100
    for (int i = threadIdx.x; i < 2 * H * H; i += blockDim.x) wu[i] = Wu[i];
    for (int i = threadIdx.x; i < H * H; i += blockDim.x) wg[i] = Wg[i];
    __syncthreads();

    int node = blockIdx.x * blockDim.x + threadIdx.x;
    if (node >= n) return;

    size_t off = (size_t)node * STRIDE;
    const float4* hr = (const float4*)(g_h + off);
    const float4* ar = (const float4*)(g_agg + off);
    float4 h0 = hr[0], h1 = hr[1], h2 = hr[2];
    float4 g0 = ar[0], g1 = ar[1], g2 = ar[2];
    float hv[H] = {h0.x, h0.y, h0.z, h0.w, h1.x, h1.y, h1.z, h1.w, h2.x, h2.y};
    float av[H] = {g0.x, g0.y, g0.z, g0.w, g1.x, g1.y, g1.z, g1.w, g2.x, g2.y};

    float o[H];
#pragma unroll
    for (int j = 0; j < H; j++) {
        float a = 0.f;
#pragma unroll
        for (int i = 0; i < H; i++) a += hv[i] * wu[i * H + j];
#pragma unroll
        for (int i = 0; i < H; i++) a += av[i] * wu[(H + i) * H + j];
        o[j] = lrelu(a);
    }

    if (out_stride == STRIDE) {
        float4* ow = (float4*)(out + (size_t)node * STRIDE);
        ow[0] = make_float4(o[0], o[1], o[2], o[3]);
        ow[1] = make_float4(o[4], o[5], o[6], o[7]);
        ow[2] = make_float4(o[8], o[9], 0.f, 0.f);
    } else {
        float2* ow = (float2*)(out + (size_t)node * H);
#pragma unroll
        for (int j = 0; j < H / 2; j++) ow[j] = make_float2(o[2 * j], o[2 * j + 1]);
    }

    if (write_p) {
        float pv[H];
#pragma unroll
        for (int j = 0; j < H; j++) {
            float a = 0.f;
#pragma unroll
            for (int i = 0; i < H; i++) a += o[i] * wg[i * H + j];
            pv[j] = a;
        }
        float4* pw = (float4*)(g_p + off);
        pw[0] = make_float4(pv[0], pv[1], pv[2], pv[3]);
        pw[1] = make_float4(pv[4], pv[5], pv[6], pv[7]);
        pw[2] = make_float4(pv[8], pv[9], 0.f, 0.f);
    }
}

// ---------------------------------------------------------------------------
extern "C" void kernel_launch(void* const* d_in, const int* in_sizes, int n_in,
                              void* d_out, int out_size) {
    const float* vertex = (const float*)d_in[0];
    const float* ef = (const float*)d_in[1];
    const int* src = (const int*)d_in[2];
    const int* dst = (const int*)d_in[3];
    const float* Wi = (const float*)d_in[4];
    const float* Wg = (const float*)d_in[5];
    const float* Wu = (const float*)d_in[6];
    float* out = (float*)d_out;

    int n = in_sizes[0] / AF;
    int e = in_sizes[2];

    void* aggp = nullptr;
    void* hp = nullptr;
    cudaGetSymbolAddress(&aggp, g_agg);
    cudaGetSymbolAddress(&hp, g_h);

    int nb256 = (n + 255) / 256;
    int ibs = (n + IB - 1) / IB;
    int pairs = (e + 1) / 2;
    int eb = (pairs + 255) / 256;

    init_kernel<<<ibs, IB>>>(vertex, Wi, Wg, n);
    for (int l = 0; l < 2; l++) {
        cudaMemsetAsync(aggp, 0, (size_t)n * STRIDE * sizeof(float));
        edge_kernel<<<eb, 256>>>((const float4*)ef, (const int2*)src,
                                 (const int2*)dst, Wg, e);
        update_kernel<<<nb256, 256>>>(Wu, Wg, (l == 1) ? out : (float*)hp, n,
                                      (l == 1) ? H : STRIDE, (l == 0) ? 1 : 0);
    }
}

// round 3
// speedup vs baseline: 1.3226x; 1.3226x over previous
#include <cuda_runtime.h>
#include <cuda_fp16.h>

#define NNODES 200000
#define AF 82
#define H 10
#define ED 6
#define STRIDE 12    // fp32 rows (h, agg): 48B
#define PSTRIDE 16   // fp16 p rows: 16 halves = 32B, sector-aligned

__device__ float g_h[(size_t)NNODES * STRIDE];
__device__ __half g_p[(size_t)NNODES * PSTRIDE];   // p = h @ Wg_top, fp16
__device__ float g_agg[(size_t)NNODES * STRIDE];

__device__ __forceinline__ float lrelu(float x) { return fmaxf(x, 0.1f * x); }

__device__ __forceinline__ void store_p_fp16(__half* pr, const float* pv) {
    __half2 t0 = __floats2half2_rn(pv[0], pv[1]);
    __half2 t1 = __floats2half2_rn(pv[2], pv[3]);
    __half2 t2 = __floats2half2_rn(pv[4], pv[5]);
    __half2 t3 = __floats2half2_rn(pv[6], pv[7]);
    __half2 t4 = __floats2half2_rn(pv[8], pv[9]);
    uint4 q;
    q.x = *(unsigned*)&t0; q.y = *(unsigned*)&t1;
    q.z = *(unsigned*)&t2; q.w = *(unsigned*)&t3;
    *(uint4*)pr = q;
    *(unsigned*)(pr + 8) = *(unsigned*)&t4;
}

__device__ __forceinline__ void load_p_fp16(const __half* pr, float* pv) {
    uint4 q = *(const uint4*)pr;
    unsigned r = *(const unsigned*)(pr + 8);
    float2 f;
    f = __half22float2(*(__half2*)&q.x); pv[0] = f.x; pv[1] = f.y;
    f = __half22float2(*(__half2*)&q.y); pv[2] = f.x; pv[3] = f.y;
    f = __half22float2(*(__half2*)&q.z); pv[4] = f.x; pv[5] = f.y;
    f = __half22float2(*(__half2*)&q.w); pv[6] = f.x; pv[7] = f.y;
    f = __half22float2(*(__half2*)&r);   pv[8] = f.x; pv[9] = f.y;
}

// ---------------------------------------------------------------------------
// init: h = lrelu(vertex @ Wi); p = h @ Wg_top.  Direct per-node reads (R1 form).
// ---------------------------------------------------------------------------
__global__ void init_kernel(const float* __restrict__ vertex,
                            const float* __restrict__ Wi,
                            const float* __restrict__ Wg, int n) {
    __shared__ float wi[AF * H];
    __shared__ float wg[H * H];
    for (int i = threadIdx.x; i < AF * H; i += blockDim.x) wi[i] = Wi[i];
    for (int i = threadIdx.x; i < H * H; i += blockDim.x) wg[i] = Wg[i];
    __syncthreads();
    int node = blockIdx.x * blockDim.x + threadIdx.x;
    if (node >= n) return;

    const float2* vr = (const float2*)(vertex + (size_t)node * AF);
    float acc[H];
#pragma unroll
    for (int j = 0; j < H; j++) acc[j] = 0.f;
#pragma unroll
    for (int i = 0; i < AF / 2; i++) {
        float2 v = vr[i];
#pragma unroll
        for (int j = 0; j < H; j++)
            acc[j] += v.x * wi[(2 * i) * H + j] + v.y * wi[(2 * i + 1) * H + j];
    }
    float h[H];
#pragma unroll
    for (int j = 0; j < H; j++) h[j] = lrelu(acc[j]);

    float pv[H];
#pragma unroll
    for (int j = 0; j < H; j++) {
        float a = 0.f;
#pragma unroll
        for (int i = 0; i < H; i++) a += h[i] * wg[i * H + j];
        pv[j] = a;
    }

    float4* hw = (float4*)(g_h + (size_t)node * STRIDE);
    hw[0] = make_float4(h[0], h[1], h[2], h[3]);
    hw[1] = make_float4(h[4], h[5], h[6], h[7]);
    hw[2] = make_float4(h[8], h[9], 0.f, 0.f);
    store_p_fp16(g_p + (size_t)node * PSTRIDE, pv);
}

// ---------------------------------------------------------------------------
// edge: msg = lrelu(p[src] + ef @ Wg_bot); agg[dst] += msg.  2 edges/thread.
// ---------------------------------------------------------------------------
__global__ void edge_kernel(const float4* __restrict__ ef4,
                            const int2* __restrict__ src2,
                            const int2* __restrict__ dst2,
                            const float* __restrict__ Wg, int ecnt) {
    __shared__ float w[ED * H];
    for (int i = threadIdx.x; i < ED * H; i += blockDim.x) w[i] = Wg[H * H + i];
    __syncthreads();

    int pr = blockIdx.x * blockDim.x + threadIdx.x;
    int e0 = 2 * pr;
    if (e0 >= ecnt) return;
    bool full = (e0 + 1) < ecnt;

    int2 s, d;
    float evA[ED], evB[ED];
    if (full) {
        s = src2[pr];
        d = dst2[pr];
        float4 f0 = ef4[3 * pr], f1 = ef4[3 * pr + 1], f2 = ef4[3 * pr + 2];
        evA[0] = f0.x; evA[1] = f0.y; evA[2] = f0.z; evA[3] = f0.w; evA[4] = f1.x; evA[5] = f1.y;
        evB[0] = f1.z; evB[1] = f1.w; evB[2] = f2.x; evB[3] = f2.y; evB[4] = f2.z; evB[5] = f2.w;
    } else {
        const int* si = (const int*)src2;
        const int* di = (const int*)dst2;
        s.x = si[e0]; s.y = s.x;
        d.x = di[e0]; d.y = d.x;
        const float* eff = (const float*)ef4;
#pragma unroll
        for (int k = 0; k < ED; k++) { evA[k] = eff[(size_t)e0 * ED + k]; evB[k] = 0.f; }
    }

    float pa[H], pb[H];
    load_p_fp16(g_p + (size_t)s.x * PSTRIDE, pa);
    load_p_fp16(g_p + (size_t)s.y * PSTRIDE, pb);

    float mA[H], mB[H];
#pragma unroll
    for (int j = 0; j < H; j++) {
        float accA = pa[j], accB = pb[j];
#pragma unroll
        for (int k = 0; k < ED; k++) {
            float wk = w[k * H + j];
            accA += evA[k] * wk;
            accB += evB[k] * wk;
        }
        mA[j] = lrelu(accA);
        mB[j] = lrelu(accB);
    }

    float* apA = g_agg + (size_t)d.x * STRIDE;
    asm volatile("red.global.add.v4.f32 [%0], {%1,%2,%3,%4};" ::"l"(apA),
                 "f"(mA[0]), "f"(mA[1]), "f"(mA[2]), "f"(mA[3]) : "memory");
    asm volatile("red.global.add.v4.f32 [%0], {%1,%2,%3,%4};" ::"l"(apA + 4),
                 "f"(mA[4]), "f"(mA[5]), "f"(mA[6]), "f"(mA[7]) : "memory");
    asm volatile("red.global.add.v2.f32 [%0], {%1,%2};" ::"l"(apA + 8),
                 "f"(mA[8]), "f"(mA[9]) : "memory");
    if (full) {
        float* apB = g_agg + (size_t)d.y * STRIDE;
        asm volatile("red.global.add.v4.f32 [%0], {%1,%2,%3,%4};" ::"l"(apB),
                     "f"(mB[0]), "f"(mB[1]), "f"(mB[2]), "f"(mB[3]) : "memory");
        asm volatile("red.global.add.v4.f32 [%0], {%1,%2,%3,%4};" ::"l"(apB + 4),
                     "f"(mB[4]), "f"(mB[5]), "f"(mB[6]), "f"(mB[7]) : "memory");
        asm volatile("red.global.add.v2.f32 [%0], {%1,%2};" ::"l"(apB + 8),
                     "f"(mB[8]), "f"(mB[9]) : "memory");
    }
}

// ---------------------------------------------------------------------------
// update: h' = lrelu(h @ Wu_top + agg @ Wu_bot); optionally p' = h' @ Wg_top
// ---------------------------------------------------------------------------
__global__ void update_kernel(const float* __restrict__ Wu,
                              const float* __restrict__ Wg,
                              float* __restrict__ out, int n,
                              int out_stride, int write_p) {
    __shared__ float wu[2 * H * H];
    __shared__ float wg[H * H];
    for (int i = threadIdx.x; i < 2 * H * H; i += blockDim.x) wu[i] = Wu[i];
    for (int i = threadIdx.x; i < H * H; i += blockDim.x) wg[i] = Wg[i];
    __syncthreads();

    int node = blockIdx.x * blockDim.x + threadIdx.x;
    if (node >= n) return;

    size_t off = (size_t)node * STRIDE;
    const float4* hr = (const float4*)(g_h + off);
    const float4* ar = (const float4*)(g_agg + off);
    float4 h0 = hr[0], h1 = hr[1], h2 = hr[2];
    float4 g0 = ar[0], g1 = ar[1], g2 = ar[2];
    float hv[H] = {h0.x, h0.y, h0.z, h0.w, h1.x, h1.y, h1.z, h1.w, h2.x, h2.y};
    float av[H] = {g0.x, g0.y, g0.z, g0.w, g1.x, g1.y, g1.z, g1.w, g2.x, g2.y};

    float o[H];
#pragma unroll
    for (int j = 0; j < H; j++) {
        float a = 0.f;
#pragma unroll
        for (int i = 0; i < H; i++) a += hv[i] * wu[i * H + j];
#pragma unroll
        for (int i = 0; i < H; i++) a += av[i] * wu[(H + i) * H + j];
        o[j] = lrelu(a);
    }

    if (out_stride == STRIDE) {
        float4* ow = (float4*)(out + (size_t)node * STRIDE);
        ow[0] = make_float4(o[0], o[1], o[2], o[3]);
        ow[1] = make_float4(o[4], o[5], o[6], o[7]);
        ow[2] = make_float4(o[8], o[9], 0.f, 0.f);
    } else {
        float2* ow = (float2*)(out + (size_t)node * H);
#pragma unroll
        for (int j = 0; j < H / 2; j++) ow[j] = make_float2(o[2 * j], o[2 * j + 1]);
    }

    if (write_p) {
        float pv[H];
#pragma unroll
        for (int j = 0; j < H; j++) {
            float a = 0.f;
#pragma unroll
            for (int i = 0; i < H; i++) a += o[i] * wg[i * H + j];
            pv[j] = a;
        }
        store_p_fp16(g_p + (size_t)node * PSTRIDE, pv);
    }
}

// ---------------------------------------------------------------------------
extern "C" void kernel_launch(void* const* d_in, const int* in_sizes, int n_in,
                              void* d_out, int out_size) {
    const float* vertex = (const float*)d_in[0];
    const float* ef = (const float*)d_in[1];
    const int* src = (const int*)d_in[2];
    const int* dst = (const int*)d_in[3];
    const float* Wi = (const float*)d_in[4];
    const float* Wg = (const float*)d_in[5];
    const float* Wu = (const float*)d_in[6];
    float* out = (float*)d_out;

    int n = in_sizes[0] / AF;
    int e = in_sizes[2];

    void* aggp = nullptr;
    void* hp = nullptr;
    cudaGetSymbolAddress(&aggp, g_agg);
    cudaGetSymbolAddress(&hp, g_h);

    int nb = (n + 255) / 256;
    int pairs = (e + 1) / 2;
    int eb = (pairs + 255) / 256;

    init_kernel<<<nb, 256>>>(vertex, Wi, Wg, n);
    for (int l = 0; l < 2; l++) {
        cudaMemsetAsync(aggp, 0, (size_t)n * STRIDE * sizeof(float));
        edge_kernel<<<eb, 256>>>((const float4*)ef, (const int2*)src,
                                 (const int2*)dst, Wg, e);
        update_kernel<<<nb, 256>>>(Wu, Wg, (l == 1) ? out : (float*)hp, n,
                                   (l == 1) ? H : STRIDE, (l == 0) ? 1 : 0);
    }
}

// round 4
// speedup vs baseline: 1.4643x; 1.1071x over previous
#include <cuda_runtime.h>
#include <cuda_fp16.h>

#define NNODES 200000
#define AF 82
#define H 10
#define ED 6
#define STRIDE 12     // fp32 h rows: 48B
#define PSTRIDE 16    // fp16 p rows: 32B
#define NPLANES 8
#define APSTRIDE 16   // fp16 agg plane rows: 32B

__device__ float g_h[(size_t)NNODES * STRIDE];
__device__ __half g_p[(size_t)NNODES * PSTRIDE];
__device__ __half g_aggh[(size_t)NPLANES * NNODES * APSTRIDE];   // 51.2MB

__device__ __forceinline__ float lrelu(float x) { return fmaxf(x, 0.1f * x); }

__device__ __forceinline__ void store_p_fp16(__half* pr, const float* pv) {
    __half2 t0 = __floats2half2_rn(pv[0], pv[1]);
    __half2 t1 = __floats2half2_rn(pv[2], pv[3]);
    __half2 t2 = __floats2half2_rn(pv[4], pv[5]);
    __half2 t3 = __floats2half2_rn(pv[6], pv[7]);
    __half2 t4 = __floats2half2_rn(pv[8], pv[9]);
    uint4 q;
    q.x = *(unsigned*)&t0; q.y = *(unsigned*)&t1;
    q.z = *(unsigned*)&t2; q.w = *(unsigned*)&t3;
    *(uint4*)pr = q;
    *(unsigned*)(pr + 8) = *(unsigned*)&t4;
}

__device__ __forceinline__ void load_p_fp16(const __half* pr, float* pv) {
    uint4 q = *(const uint4*)pr;
    unsigned r = *(const unsigned*)(pr + 8);
    float2 f;
    f = __half22float2(*(__half2*)&q.x); pv[0] = f.x; pv[1] = f.y;
    f = __half22float2(*(__half2*)&q.y); pv[2] = f.x; pv[3] = f.y;
    f = __half22float2(*(__half2*)&q.z); pv[4] = f.x; pv[5] = f.y;
    f = __half22float2(*(__half2*)&q.w); pv[6] = f.x; pv[7] = f.y;
    f = __half22float2(*(__half2*)&r);   pv[8] = f.x; pv[9] = f.y;
}

// scatter msg (fp32) into fp16 plane row with 2 RED instructions
__device__ __forceinline__ void red_msg_fp16(__half* ap, const float* m) {
    __half2 h0 = __floats2half2_rn(m[0], m[1]);
    __half2 h1 = __floats2half2_rn(m[2], m[3]);
    __half2 h2 = __floats2half2_rn(m[4], m[5]);
    __half2 h3 = __floats2half2_rn(m[6], m[7]);
    __half2 h4 = __floats2half2_rn(m[8], m[9]);
    asm volatile("red.global.add.noftz.v4.f16x2 [%0], {%1,%2,%3,%4};" ::
                 "l"(ap), "r"(*(unsigned*)&h0), "r"(*(unsigned*)&h1),
                 "r"(*(unsigned*)&h2), "r"(*(unsigned*)&h3) : "memory");
    asm volatile("red.global.add.noftz.f16x2 [%0], %1;" ::
                 "l"(ap + 8), "r"(*(unsigned*)&h4) : "memory");
}

// ---------------------------------------------------------------------------
// init: h = lrelu(vertex @ Wi); p = h @ Wg_top
// ---------------------------------------------------------------------------
__global__ void init_kernel(const float* __restrict__ vertex,
                            const float* __restrict__ Wi,
                            const float* __restrict__ Wg, int n) {
    __shared__ float wi[AF * H];
    __shared__ float wg[H * H];
    for (int i = threadIdx.x; i < AF * H; i += blockDim.x) wi[i] = Wi[i];
    for (int i = threadIdx.x; i < H * H; i += blockDim.x) wg[i] = Wg[i];
    __syncthreads();
    int node = blockIdx.x * blockDim.x + threadIdx.x;
    if (node >= n) return;

    const float2* vr = (const float2*)(vertex + (size_t)node * AF);
    float acc[H];
#pragma unroll
    for (int j = 0; j < H; j++) acc[j] = 0.f;
#pragma unroll
    for (int i = 0; i < AF / 2; i++) {
        float2 v = vr[i];
#pragma unroll
        for (int j = 0; j < H; j++)
            acc[j] += v.x * wi[(2 * i) * H + j] + v.y * wi[(2 * i + 1) * H + j];
    }
    float h[H];
#pragma unroll
    for (int j = 0; j < H; j++) h[j] = lrelu(acc[j]);

    float pv[H];
#pragma unroll
    for (int j = 0; j < H; j++) {
        float a = 0.f;
#pragma unroll
        for (int i = 0; i < H; i++) a += h[i] * wg[i * H + j];
        pv[j] = a;
    }

    float4* hw = (float4*)(g_h + (size_t)node * STRIDE);
    hw[0] = make_float4(h[0], h[1], h[2], h[3]);
    hw[1] = make_float4(h[4], h[5], h[6], h[7]);
    hw[2] = make_float4(h[8], h[9], 0.f, 0.f);
    store_p_fp16(g_p + (size_t)node * PSTRIDE, pv);
}

// ---------------------------------------------------------------------------
// edge: msg = lrelu(p[src] + ef @ Wg_bot); fp16 plane scatter. 2 edges/thread.
// ---------------------------------------------------------------------------
__global__ void __launch_bounds__(256, 5)
edge_kernel(const float4* __restrict__ ef4,
            const int2* __restrict__ src2,
            const int2* __restrict__ dst2,
            const float* __restrict__ Wg, int ecnt) {
    __shared__ float w[ED * H];
    for (int i = threadIdx.x; i < ED * H; i += blockDim.x) w[i] = Wg[H * H + i];
    __syncthreads();

    int pr = blockIdx.x * blockDim.x + threadIdx.x;
    int e0 = 2 * pr;
    if (e0 >= ecnt) return;
    bool full = (e0 + 1) < ecnt;

    int2 s, d;
    float evA[ED], evB[ED];
    if (full) {
        s = src2[pr];
        d = dst2[pr];
        float4 f0 = ef4[3 * pr], f1 = ef4[3 * pr + 1], f2 = ef4[3 * pr + 2];
        evA[0] = f0.x; evA[1] = f0.y; evA[2] = f0.z; evA[3] = f0.w; evA[4] = f1.x; evA[5] = f1.y;
        evB[0] = f1.z; evB[1] = f1.w; evB[2] = f2.x; evB[3] = f2.y; evB[4] = f2.z; evB[5] = f2.w;
    } else {
        const int* si = (const int*)src2;
        const int* di = (const int*)dst2;
        s.x = si[e0]; s.y = s.x;
        d.x = di[e0]; d.y = d.x;
        const float* eff = (const float*)ef4;
#pragma unroll
        for (int k = 0; k < ED; k++) { evA[k] = eff[(size_t)e0 * ED + k]; evB[k] = 0.f; }
    }

    float pa[H], pb[H];
    load_p_fp16(g_p + (size_t)s.x * PSTRIDE, pa);
    load_p_fp16(g_p + (size_t)s.y * PSTRIDE, pb);

    float mA[H], mB[H];
#pragma unroll
    for (int j = 0; j < H; j++) {
        float accA = pa[j], accB = pb[j];
#pragma unroll
        for (int k = 0; k < ED; k++) {
            float wk = w[k * H + j];
            accA += evA[k] * wk;
            accB += evB[k] * wk;
        }
        mA[j] = lrelu(accA);
        mB[j] = lrelu(accB);
    }

    // planes: edge e0 -> 2*(pr&3), edge e0+1 -> 2*(pr&3)+1  (uniform over 8)
    int pA = (pr & 3) * 2;
    __half* apA = g_aggh + ((size_t)pA * NNODES + d.x) * APSTRIDE;
    red_msg_fp16(apA, mA);
    if (full) {
        __half* apB = g_aggh + ((size_t)(pA + 1) * NNODES + d.y) * APSTRIDE;
        red_msg_fp16(apB, mB);
    }
}

// ---------------------------------------------------------------------------
// update: agg = sum of 8 fp16 planes; h' = lrelu(h @ Wu_top + agg @ Wu_bot)
// ---------------------------------------------------------------------------
__global__ void update_kernel(const float* __restrict__ Wu,
                              const float* __restrict__ Wg,
                              float* __restrict__ out, int n,
                              int out_stride, int write_p) {
    __shared__ float wu[2 * H * H];
    __shared__ float wg[H * H];
    for (int i = threadIdx.x; i < 2 * H * H; i += blockDim.x) wu[i] = Wu[i];
    for (int i = threadIdx.x; i < H * H; i += blockDim.x) wg[i] = Wg[i];
    __syncthreads();

    int node = blockIdx.x * blockDim.x + threadIdx.x;
    if (node >= n) return;

    size_t off = (size_t)node * STRIDE;
    const float4* hr = (const float4*)(g_h + off);
    float4 h0 = hr[0], h1 = hr[1], h2 = hr[2];
    float hv[H] = {h0.x, h0.y, h0.z, h0.w, h1.x, h1.y, h1.z, h1.w, h2.x, h2.y};

    float av[H];
#pragma unroll
    for (int j = 0; j < H; j++) av[j] = 0.f;
#pragma unroll
    for (int pl = 0; pl < NPLANES; pl++) {
        const __half* ar = g_aggh + ((size_t)pl * NNODES + node) * APSTRIDE;
        uint4 q = *(const uint4*)ar;
        unsigned t = *(const unsigned*)(ar + 8);
        float2 f;
        f = __half22float2(*(__half2*)&q.x); av[0] += f.x; av[1] += f.y;
        f = __half22float2(*(__half2*)&q.y); av[2] += f.x; av[3] += f.y;
        f = __half22float2(*(__half2*)&q.z); av[4] += f.x; av[5] += f.y;
        f = __half22float2(*(__half2*)&q.w); av[6] += f.x; av[7] += f.y;
        f = __half22float2(*(__half2*)&t);   av[8] += f.x; av[9] += f.y;
    }

    float o[H];
#pragma unroll
    for (int j = 0; j < H; j++) {
        float a = 0.f;
#pragma unroll
        for (int i = 0; i < H; i++) a += hv[i] * wu[i * H + j];
#pragma unroll
        for (int i = 0; i < H; i++) a += av[i] * wu[(H + i) * H + j];
        o[j] = lrelu(a);
    }

    if (out_stride == STRIDE) {
        float4* ow = (float4*)(out + (size_t)node * STRIDE);
        ow[0] = make_float4(o[0], o[1], o[2], o[3]);
        ow[1] = make_float4(o[4], o[5], o[6], o[7]);
        ow[2] = make_float4(o[8], o[9], 0.f, 0.f);
    } else {
        float2* ow = (float2*)(out + (size_t)node * H);
#pragma unroll
        for (int j = 0; j < H / 2; j++) ow[j] = make_float2(o[2 * j], o[2 * j + 1]);
    }

    if (write_p) {
        float pv[H];
#pragma unroll
        for (int j = 0; j < H; j++) {
            float a = 0.f;
#pragma unroll
            for (int i = 0; i < H; i++) a += o[i] * wg[i * H + j];
            pv[j] = a;
        }
        store_p_fp16(g_p + (size_t)node * PSTRIDE, pv);
    }
}

// ---------------------------------------------------------------------------
extern "C" void kernel_launch(void* const* d_in, const int* in_sizes, int n_in,
                              void* d_out, int out_size) {
    const float* vertex = (const float*)d_in[0];
    const float* ef = (const float*)d_in[1];
    const int* src = (const int*)d_in[2];
    const int* dst = (const int*)d_in[3];
    const float* Wi = (const float*)d_in[4];
    const float* Wg = (const float*)d_in[5];
    const float* Wu = (const float*)d_in[6];
    float* out = (float*)d_out;

    int n = in_sizes[0] / AF;
    int e = in_sizes[2];

    void* aggp = nullptr;
    void* hp = nullptr;
    cudaGetSymbolAddress(&aggp, g_aggh);
    cudaGetSymbolAddress(&hp, g_h);

    int nb = (n + 255) / 256;
    int pairs = (e + 1) / 2;
    int eb = (pairs + 255) / 256;
    size_t aggbytes = (size_t)NPLANES * NNODES * APSTRIDE * sizeof(__half);

    init_kernel<<<nb, 256>>>(vertex, Wi, Wg, n);
    for (int l = 0; l < 2; l++) {
        cudaMemsetAsync(aggp, 0, aggbytes);
        edge_kernel<<<eb, 256>>>((const float4*)ef, (const int2*)src,
                                 (const int2*)dst, Wg, e);
        update_kernel<<<nb, 256>>>(Wu, Wg, (l == 1) ? out : (float*)hp, n,
                                   (l == 1) ? H : STRIDE, (l == 0) ? 1 : 0);
    }
}

// round 5
// speedup vs baseline: 1.5302x; 1.0450x over previous
#include <cuda_runtime.h>
#include <cuda_fp16.h>

#define NNODES 200000
#define AF 82
#define H 10
#define ED 6
#define STRIDE 12     // fp32 h rows: 48B
#define PSTRIDE 16    // fp16 p rows: 32B
#define NPLANES 4
#define APSTRIDE 16   // fp16 agg plane rows: 32B

__device__ float g_h[(size_t)NNODES * STRIDE];
__device__ __half g_p[(size_t)NNODES * PSTRIDE];
__device__ __half g_aggh[(size_t)NPLANES * NNODES * APSTRIDE];   // 25.6MB

__device__ __forceinline__ float lrelu(float x) { return fmaxf(x, 0.1f * x); }

__device__ __forceinline__ void store_p_fp16(__half* pr, const float* pv) {
    __half2 t0 = __floats2half2_rn(pv[0], pv[1]);
    __half2 t1 = __floats2half2_rn(pv[2], pv[3]);
    __half2 t2 = __floats2half2_rn(pv[4], pv[5]);
    __half2 t3 = __floats2half2_rn(pv[6], pv[7]);
    __half2 t4 = __floats2half2_rn(pv[8], pv[9]);
    uint4 q;
    q.x = *(unsigned*)&t0; q.y = *(unsigned*)&t1;
    q.z = *(unsigned*)&t2; q.w = *(unsigned*)&t3;
    *(uint4*)pr = q;
    *(unsigned*)(pr + 8) = *(unsigned*)&t4;
}

__device__ __forceinline__ void load_p_fp16(const __half* pr, float* pv) {
    uint4 q = *(const uint4*)pr;
    unsigned r = *(const unsigned*)(pr + 8);
    float2 f;
    f = __half22float2(*(__half2*)&q.x); pv[0] = f.x; pv[1] = f.y;
    f = __half22float2(*(__half2*)&q.y); pv[2] = f.x; pv[3] = f.y;
    f = __half22float2(*(__half2*)&q.z); pv[4] = f.x; pv[5] = f.y;
    f = __half22float2(*(__half2*)&q.w); pv[6] = f.x; pv[7] = f.y;
    f = __half22float2(*(__half2*)&r);   pv[8] = f.x; pv[9] = f.y;
}

__device__ __forceinline__ void red_msg_fp16(__half* ap, const float* m) {
    __half2 h0 = __floats2half2_rn(m[0], m[1]);
    __half2 h1 = __floats2half2_rn(m[2], m[3]);
    __half2 h2 = __floats2half2_rn(m[4], m[5]);
    __half2 h3 = __floats2half2_rn(m[6], m[7]);
    __half2 h4 = __floats2half2_rn(m[8], m[9]);
    asm volatile("red.global.add.noftz.v4.f16x2 [%0], {%1,%2,%3,%4};" ::
                 "l"(ap), "r"(*(unsigned*)&h0), "r"(*(unsigned*)&h1),
                 "r"(*(unsigned*)&h2), "r"(*(unsigned*)&h3) : "memory");
    asm volatile("red.global.add.noftz.f16x2 [%0], %1;" ::
                 "l"(ap + 8), "r"(*(unsigned*)&h4) : "memory");
}

__device__ __forceinline__ void zero_planes(int node) {
    uint4 z = make_uint4(0, 0, 0, 0);
#pragma unroll
    for (int pl = 0; pl < NPLANES; pl++) {
        __half* ar = g_aggh + ((size_t)pl * NNODES + node) * APSTRIDE;
        ((uint4*)ar)[0] = z;
        ((uint4*)ar)[1] = z;
    }
}

// ---------------------------------------------------------------------------
// init: h = lrelu(vertex @ Wi); p = h @ Wg_top; zero agg planes (layer-0 prep)
// ---------------------------------------------------------------------------
__global__ void init_kernel(const float* __restrict__ vertex,
                            const float* __restrict__ Wi,
                            const float* __restrict__ Wg, int n) {
    __shared__ float wi[AF * H];
    __shared__ float wg[H * H];
    for (int i = threadIdx.x; i < AF * H; i += blockDim.x) wi[i] = Wi[i];
    for (int i = threadIdx.x; i < H * H; i += blockDim.x) wg[i] = Wg[i];
    __syncthreads();
    int node = blockIdx.x * blockDim.x + threadIdx.x;
    if (node >= n) return;

    zero_planes(node);

    const float2* vr = (const float2*)(vertex + (size_t)node * AF);
    float acc[H];
#pragma unroll
    for (int j = 0; j < H; j++) acc[j] = 0.f;
#pragma unroll
    for (int i = 0; i < AF / 2; i++) {
        float2 v = vr[i];
#pragma unroll
        for (int j = 0; j < H; j++)
            acc[j] += v.x * wi[(2 * i) * H + j] + v.y * wi[(2 * i + 1) * H + j];
    }
    float h[H];
#pragma unroll
    for (int j = 0; j < H; j++) h[j] = lrelu(acc[j]);

    float pv[H];
#pragma unroll
    for (int j = 0; j < H; j++) {
        float a = 0.f;
#pragma unroll
        for (int i = 0; i < H; i++) a += h[i] * wg[i * H + j];
        pv[j] = a;
    }

    float4* hw = (float4*)(g_h + (size_t)node * STRIDE);
    hw[0] = make_float4(h[0], h[1], h[2], h[3]);
    hw[1] = make_float4(h[4], h[5], h[6], h[7]);
    hw[2] = make_float4(h[8], h[9], 0.f, 0.f);
    store_p_fp16(g_p + (size_t)node * PSTRIDE, pv);
}

// ---------------------------------------------------------------------------
// edge: msg = lrelu(p[src] + ef @ Wg_bot); fp16 plane scatter. 2 edges/thread.
// ---------------------------------------------------------------------------
__global__ void __launch_bounds__(256, 6)
edge_kernel(const float4* __restrict__ ef4,
            const int2* __restrict__ src2,
            const int2* __restrict__ dst2,
            const float* __restrict__ Wg, int ecnt) {
    __shared__ float w[ED * H];
    for (int i = threadIdx.x; i < ED * H; i += blockDim.x) w[i] = Wg[H * H + i];
    __syncthreads();

    int pr = blockIdx.x * blockDim.x + threadIdx.x;
    int e0 = 2 * pr;
    if (e0 >= ecnt) return;
    bool full = (e0 + 1) < ecnt;

    int2 s, d;
    float evA[ED], evB[ED];
    if (full) {
        s = src2[pr];
        d = dst2[pr];
        float4 f0 = ef4[3 * pr], f1 = ef4[3 * pr + 1], f2 = ef4[3 * pr + 2];
        evA[0] = f0.x; evA[1] = f0.y; evA[2] = f0.z; evA[3] = f0.w; evA[4] = f1.x; evA[5] = f1.y;
        evB[0] = f1.z; evB[1] = f1.w; evB[2] = f2.x; evB[3] = f2.y; evB[4] = f2.z; evB[5] = f2.w;
    } else {
        const int* si = (const int*)src2;
        const int* di = (const int*)dst2;
        s.x = si[e0]; s.y = s.x;
        d.x = di[e0]; d.y = d.x;
        const float* eff = (const float*)ef4;
#pragma unroll
        for (int k = 0; k < ED; k++) { evA[k] = eff[(size_t)e0 * ED + k]; evB[k] = 0.f; }
    }

    float pa[H], pb[H];
    load_p_fp16(g_p + (size_t)s.x * PSTRIDE, pa);
    load_p_fp16(g_p + (size_t)s.y * PSTRIDE, pb);

    float mA[H], mB[H];
#pragma unroll
    for (int j = 0; j < H; j++) {
        float accA = pa[j], accB = pb[j];
#pragma unroll
        for (int k = 0; k < ED; k++) {
            float wk = w[k * H + j];
            accA += evA[k] * wk;
            accB += evB[k] * wk;
        }
        mA[j] = lrelu(accA);
        mB[j] = lrelu(accB);
    }

    // planes: edge A -> 2*(pr&1), edge B -> 2*(pr&1)+1  (uniform over 4)
    int pA = (pr & 1) * 2;
    __half* apA = g_aggh + ((size_t)pA * NNODES + d.x) * APSTRIDE;
    red_msg_fp16(apA, mA);
    if (full) {
        __half* apB = g_aggh + ((size_t)(pA + 1) * NNODES + d.y) * APSTRIDE;
        red_msg_fp16(apB, mB);
    }
}

// ---------------------------------------------------------------------------
// update: agg = sum of 4 fp16 planes; h' = lrelu(h @ Wu_top + agg @ Wu_bot);
// layer 0: also write p' and re-zero planes for next layer
// ---------------------------------------------------------------------------
__global__ void update_kernel(const float* __restrict__ Wu,
                              const float* __restrict__ Wg,
                              float* __restrict__ out, int n,
                              int out_stride, int write_p) {
    __shared__ float wu[2 * H * H];
    __shared__ float wg[H * H];
    for (int i = threadIdx.x; i < 2 * H * H; i += blockDim.x) wu[i] = Wu[i];
    for (int i = threadIdx.x; i < H * H; i += blockDim.x) wg[i] = Wg[i];
    __syncthreads();

    int node = blockIdx.x * blockDim.x + threadIdx.x;
    if (node >= n) return;

    size_t off = (size_t)node * STRIDE;
    const float4* hr = (const float4*)(g_h + off);
    float4 h0 = hr[0], h1 = hr[1], h2 = hr[2];
    float hv[H] = {h0.x, h0.y, h0.z, h0.w, h1.x, h1.y, h1.z, h1.w, h2.x, h2.y};

    float av[H];
#pragma unroll
    for (int j = 0; j < H; j++) av[j] = 0.f;
#pragma unroll
    for (int pl = 0; pl < NPLANES; pl++) {
        const __half* ar = g_aggh + ((size_t)pl * NNODES + node) * APSTRIDE;
        uint4 q = *(const uint4*)ar;
        unsigned t = *(const unsigned*)(ar + 8);
        float2 f;
        f = __half22float2(*(__half2*)&q.x); av[0] += f.x; av[1] += f.y;
        f = __half22float2(*(__half2*)&q.y); av[2] += f.x; av[3] += f.y;
        f = __half22float2(*(__half2*)&q.z); av[4] += f.x; av[5] += f.y;
        f = __half22float2(*(__half2*)&q.w); av[6] += f.x; av[7] += f.y;
        f = __half22float2(*(__half2*)&t);   av[8] += f.x; av[9] += f.y;
    }

    if (write_p) zero_planes(node);   // prep planes for next layer

    float o[H];
#pragma unroll
    for (int j = 0; j < H; j++) {
        float a = 0.f;
#pragma unroll
        for (int i = 0; i < H; i++) a += hv[i] * wu[i * H + j];
#pragma unroll
        for (int i = 0; i < H; i++) a += av[i] * wu[(H + i) * H + j];
        o[j] = lrelu(a);
    }

    if (out_stride == STRIDE) {
        float4* ow = (float4*)(out + (size_t)node * STRIDE);
        ow[0] = make_float4(o[0], o[1], o[2], o[3]);
        ow[1] = make_float4(o[4], o[5], o[6], o[7]);
        ow[2] = make_float4(o[8], o[9], 0.f, 0.f);
    } else {
        float2* ow = (float2*)(out + (size_t)node * H);
#pragma unroll
        for (int j = 0; j < H / 2; j++) ow[j] = make_float2(o[2 * j], o[2 * j + 1]);
    }

    if (write_p) {
        float pv[H];
#pragma unroll
        for (int j = 0; j < H; j++) {
            float a = 0.f;
#pragma unroll
            for (int i = 0; i < H; i++) a += o[i] * wg[i * H + j];
            pv[j] = a;
        }
        store_p_fp16(g_p + (size_t)node * PSTRIDE, pv);
    }
}

// ---------------------------------------------------------------------------
extern "C" void kernel_launch(void* const* d_in, const int* in_sizes, int n_in,
                              void* d_out, int out_size) {
    const float* vertex = (const float*)d_in[0];
    const float* ef = (const float*)d_in[1];
    const int* src = (const int*)d_in[2];
    const int* dst = (const int*)d_in[3];
    const float* Wi = (const float*)d_in[4];
    const float* Wg = (const float*)d_in[5];
    const float* Wu = (const float*)d_in[6];
    float* out = (float*)d_out;

    int n = in_sizes[0] / AF;
    int e = in_sizes[2];

    void* hp = nullptr;
    cudaGetSymbolAddress(&hp, g_h);

    int nb = (n + 255) / 256;
    int pairs = (e + 1) / 2;
    int eb = (pairs + 255) / 256;

    init_kernel<<<nb, 256>>>(vertex, Wi, Wg, n);
    for (int l = 0; l < 2; l++) {
        edge_kernel<<<eb, 256>>>((const float4*)ef, (const int2*)src,
                                 (const int2*)dst, Wg, e);
        update_kernel<<<nb, 256>>>(Wu, Wg, (l == 1) ? out : (float*)hp, n,
                                   (l == 1) ? H : STRIDE, (l == 0) ? 1 : 0);
    }
}

// round 7
// speedup vs baseline: 1.6913x; 1.1053x over previous
#include <cuda_runtime.h>
#include <cuda_fp16.h>

#define NNODES 200000
#define AF 82
#define H 10
#define ED 6
#define STRIDE 12     // fp32 h rows: 48B
#define PSTRIDE 16    // fp16 p rows: 32B (halves 10..15 are permanent zeros)
#define NPLANES 4
#define APSTRIDE 16   // fp16 agg plane rows: 32B

__device__ float g_h[(size_t)NNODES * STRIDE];
__device__ __half g_p[(size_t)NNODES * PSTRIDE];                 // zero-init pads
__device__ __half g_aggh[(size_t)NPLANES * NNODES * APSTRIDE];   // 25.6MB

__device__ __forceinline__ float lrelu(float x) { return fmaxf(x, 0.1f * x); }

__device__ __forceinline__ void store_p_fp16(__half* pr, const float* pv) {
    __half2 t0 = __floats2half2_rn(pv[0], pv[1]);
    __half2 t1 = __floats2half2_rn(pv[2], pv[3]);
    __half2 t2 = __floats2half2_rn(pv[4], pv[5]);
    __half2 t3 = __floats2half2_rn(pv[6], pv[7]);
    __half2 t4 = __floats2half2_rn(pv[8], pv[9]);
    uint4 q;
    q.x = *(unsigned*)&t0; q.y = *(unsigned*)&t1;
    q.z = *(unsigned*)&t2; q.w = *(unsigned*)&t3;
    *(uint4*)pr = q;
    // halves 8..15: dims 8,9 then zero pad (keeps role-1 LDG.128 exact)
    uint4 q2;
    q2.x = *(unsigned*)&t4; q2.y = 0u; q2.z = 0u; q2.w = 0u;
    *(uint4*)(pr + 8) = q2;
}

__device__ __forceinline__ void zero_planes(int node) {
    uint4 z = make_uint4(0, 0, 0, 0);
#pragma unroll
    for (int pl = 0; pl < NPLANES; pl++) {
        __half* ar = g_aggh + ((size_t)pl * NNODES + node) * APSTRIDE;
        ((uint4*)ar)[0] = z;
        ((uint4*)ar)[1] = z;
    }
}

// ---------------------------------------------------------------------------
// init: h = lrelu(vertex @ Wi); p = h @ Wg_top; zero agg planes (layer-0 prep)
// float4 row reads with even/odd alignment fixup (row start = node*328B).
// ---------------------------------------------------------------------------
__global__ void init_kernel(const float* __restrict__ vertex,
                            const float* __restrict__ Wi,
                            const float* __restrict__ Wg, int n) {
    __shared__ float wi[AF * H];
    __shared__ float wg[H * H];
    for (int i = threadIdx.x; i < AF * H; i += blockDim.x) wi[i] = Wi[i];
    for (int i = threadIdx.x; i < H * H; i += blockDim.x) wg[i] = Wg[i];
    __syncthreads();
    int node = blockIdx.x * blockDim.x + threadIdx.x;
    if (node >= n) return;

    zero_planes(node);

    const float* row = vertex + (size_t)node * AF;
    float acc[H];
#pragma unroll
    for (int j = 0; j < H; j++) acc[j] = 0.f;

    int base = (node & 1) ? 2 : 0;   // odd rows are 8B-aligned: peel 2 floats
    if (node & 1) {
        float2 hd = *(const float2*)row;
#pragma unroll
        for (int j = 0; j < H; j++)
            acc[j] += hd.x * wi[0 * H + j] + hd.y * wi[1 * H + j];
    }
    const float4* r4 = (const float4*)(row + base);
    const float* wb = wi + base * H;
#pragma unroll
    for (int i = 0; i < 20; i++) {
        float4 v = r4[i];
        const float* wk = wb + (4 * i) * H;
#pragma unroll
        for (int j = 0; j < H; j++)
            acc[j] += v.x * wk[j] + v.y * wk[H + j] +
                      v.z * wk[2 * H + j] + v.w * wk[3 * H + j];
    }
    if (!(node & 1)) {
        float2 tl = *(const float2*)(row + 80);
#pragma unroll
        for (int j = 0; j < H; j++)
            acc[j] += tl.x * wi[80 * H + j] + tl.y * wi[81 * H + j];
    }

    float h[H];
#pragma unroll
    for (int j = 0; j < H; j++) h[j] = lrelu(acc[j]);

    float pv[H];
#pragma unroll
    for (int j = 0; j < H; j++) {
        float a = 0.f;
#pragma unroll
        for (int i = 0; i < H; i++) a += h[i] * wg[i * H + j];
        pv[j] = a;
    }

    float4* hw = (float4*)(g_h + (size_t)node * STRIDE);
    hw[0] = make_float4(h[0], h[1], h[2], h[3]);
    hw[1] = make_float4(h[4], h[5], h[6], h[7]);
    hw[2] = make_float4(h[8], h[9], 0.f, 0.f);
    store_p_fp16(g_p + (size_t)node * PSTRIDE, pv);
}

// ---------------------------------------------------------------------------
// edge: 2 lanes per edge (role = tid&1). Each lane: one LDG.128 p-gather of its
// 16B half-row, 8 output dims, one red.v4.f16x2 into its 16B half of the agg
// row. Pair lanes hit the same 128B line -> ~1 wavefront/edge per instruction.
// Role 1 dims 10..15 are exact zeros (zero-padded p row + zero-padded weights).
// ---------------------------------------------------------------------------
__global__ void __launch_bounds__(256, 8)
edge_kernel(const float* __restrict__ ef,
            const int* __restrict__ src,
            const int* __restrict__ dst,
            const float* __restrict__ Wg, int ecnt) {
    __shared__ float wpad[ED][16];   // wpad[k][j] = Wg[(H+k)*H + j] for j<10 else 0
    for (int i = threadIdx.x; i < ED * 16; i += blockDim.x) {
        int k = i >> 4, j = i & 15;
        wpad[k][j] = (j < H) ? Wg[(H + k) * H + j] : 0.f;
    }
    __syncthreads();

    int tid = blockIdx.x * blockDim.x + threadIdx.x;
    int e = tid >> 1;
    int role = tid & 1;
    if (e >= ecnt) return;

    int s = src[e];
    int d = dst[e];

    // edge features: pairwise-broadcast 3x float2 (8B-aligned)
    const float2* ep = (const float2*)(ef + (size_t)e * ED);
    float2 f0 = ep[0], f1 = ep[1], f2 = ep[2];
    float ev[ED] = {f0.x, f0.y, f1.x, f1.y, f2.x, f2.y};

    // gather this role's 16B half of the p row
    const __half* pr = g_p + (size_t)s * PSTRIDE + role * 8;
    uint4 q = *(const uint4*)pr;
    float pl[8];
    {
        float2 f;
        f = __half22float2(*(__half2*)&q.x); pl[0] = f.x; pl[1] = f.y;
        f = __half22float2(*(__half2*)&q.y); pl[2] = f.x; pl[3] = f.y;
        f = __half22float2(*(__half2*)&q.z); pl[4] = f.x; pl[5] = f.y;
        f = __half22float2(*(__half2*)&q.w); pl[6] = f.x; pl[7] = f.y;
    }

    const float* wj = &wpad[0][role * 8];
    float m[8];
#pragma unroll
    for (int jj = 0; jj < 8; jj++) {
        float a = pl[jj];
#pragma unroll
        for (int k = 0; k < ED; k++) a += ev[k] * wj[k * 16 + jj];
        m[jj] = lrelu(a);
    }

    __half2 h0 = __floats2half2_rn(m[0], m[1]);
    __half2 h1 = __floats2half2_rn(m[2], m[3]);
    __half2 h2 = __floats2half2_rn(m[4], m[5]);
    __half2 h3 = __floats2half2_rn(m[6], m[7]);

    int plane = e & (NPLANES - 1);
    __half* ap = g_aggh + ((size_t)plane * NNODES + d) * APSTRIDE + role * 8;
    asm volatile("red.global.add.noftz.v4.f16x2 [%0], {%1,%2,%3,%4};" ::
                 "l"(ap), "r"(*(unsigned*)&h0), "r"(*(unsigned*)&h1),
                 "r"(*(unsigned*)&h2), "r"(*(unsigned*)&h3) : "memory");
}

// ---------------------------------------------------------------------------
// update: agg = sum of 4 fp16 planes; h' = lrelu(h @ Wu_top + agg @ Wu_bot);
// layer 0: also write p' and re-zero planes for next layer
// ---------------------------------------------------------------------------
__global__ void update_kernel(const float* __restrict__ Wu,
                              const float* __restrict__ Wg,
                              float* __restrict__ out, int n,
                              int out_stride, int write_p) {
    __shared__ float wu[2 * H * H];
    __shared__ float wg[H * H];
    for (int i = threadIdx.x; i < 2 * H * H; i += blockDim.x) wu[i] = Wu[i];
    for (int i = threadIdx.x; i < H * H; i += blockDim.x) wg[i] = Wg[i];
    __syncthreads();

    int node = blockIdx.x * blockDim.x + threadIdx.x;
    if (node >= n) return;

    size_t off = (size_t)node * STRIDE;
    const float4* hr = (const float4*)(g_h + off);
    float4 h0 = hr[0], h1 = hr[1], h2 = hr[2];
    float hv[H] = {h0.x, h0.y, h0.z, h0.w, h1.x, h1.y, h1.z, h1.w, h2.x, h2.y};

    float av[H];
#pragma unroll
    for (int j = 0; j < H; j++) av[j] = 0.f;
#pragma unroll
    for (int pl = 0; pl < NPLANES; pl++) {
        const __half* ar = g_aggh + ((size_t)pl * NNODES + node) * APSTRIDE;
        uint4 q = *(const uint4*)ar;
        unsigned t = *(const unsigned*)(ar + 8);
        float2 f;
        f = __half22float2(*(__half2*)&q.x); av[0] += f.x; av[1] += f.y;
        f = __half22float2(*(__half2*)&q.y); av[2] += f.x; av[3] += f.y;
        f = __half22float2(*(__half2*)&q.z); av[4] += f.x; av[5] += f.y;
        f = __half22float2(*(__half2*)&q.w); av[6] += f.x; av[7] += f.y;
        f = __half22float2(*(__half2*)&t);   av[8] += f.x; av[9] += f.y;
    }

    if (write_p) zero_planes(node);   // prep planes for next layer

    float o[H];
#pragma unroll
    for (int j = 0; j < H; j++) {
        float a = 0.f;
#pragma unroll
        for (int i = 0; i < H; i++) a += hv[i] * wu[i * H + j];
#pragma unroll
        for (int i = 0; i < H; i++) a += av[i] * wu[(H + i) * H + j];
        o[j] = lrelu(a);
    }

    if (out_stride == STRIDE) {
        float4* ow = (float4*)(out + (size_t)node * STRIDE);
        ow[0] = make_float4(o[0], o[1], o[2], o[3]);
        ow[1] = make_float4(o[4], o[5], o[6], o[7]);
        ow[2] = make_float4(o[8], o[9], 0.f, 0.f);
    } else {
        float2* ow = (float2*)(out + (size_t)node * H);
#pragma unroll
        for (int j = 0; j < H / 2; j++) ow[j] = make_float2(o[2 * j], o[2 * j + 1]);
    }

    if (write_p) {
        float pv[H];
#pragma unroll
        for (int j = 0; j < H; j++) {
            float a = 0.f;
#pragma unroll
            for (int i = 0; i < H; i++) a += o[i] * wg[i * H + j];
            pv[j] = a;
        }
        store_p_fp16(g_p + (size_t)node * PSTRIDE, pv);
    }
}

// ---------------------------------------------------------------------------
extern "C" void kernel_launch(void* const* d_in, const int* in_sizes, int n_in,
                              void* d_out, int out_size) {
    const float* vertex = (const float*)d_in[0];
    const float* ef = (const float*)d_in[1];
    const int* src = (const int*)d_in[2];
    const int* dst = (const int*)d_in[3];
    const float* Wi = (const float*)d_in[4];
    const float* Wg = (const float*)d_in[5];
    const float* Wu = (const float*)d_in[6];
    float* out = (float*)d_out;

    int n = in_sizes[0] / AF;
    int e = in_sizes[2];

    void* hp = nullptr;
    cudaGetSymbolAddress(&hp, g_h);

    int nb = (n + 255) / 256;
    long long lanes = 2LL * e;
    int eb = (int)((lanes + 255) / 256);

    init_kernel<<<nb, 256>>>(vertex, Wi, Wg, n);
    for (int l = 0; l < 2; l++) {
        edge_kernel<<<eb, 256>>>(ef, src, dst, Wg, e);
        update_kernel<<<nb, 256>>>(Wu, Wg, (l == 1) ? out : (float*)hp, n,
                                   (l == 1) ? H : STRIDE, (l == 0) ? 1 : 0);
    }
}